// round 14
// baseline (speedup 1.0000x reference)
#include <cuda_runtime.h>
#include <math.h>
#include <stdint.h>

#define HEAD_DIM   128
#define NUM_HEADS  32
#define KVH        8
#define G          4
#define BLOCK_SZ   16
#define D_KV       (KVH * HEAD_DIM)
#define MAX_BPS    128
#define MAX_CTX    2048
#define BATCH      32
#define CHUNK      384                      // 24 cache blocks -> ~810 live CTAs = 1 wave
#define NCHUNK     6                        // ceil(2048/384)
#define NBLK       (CHUNK / BLOCK_SZ)       // 24
#define SCALE_F    0.08838834764831845f

typedef unsigned long long ull;

__device__ float g_pm  [BATCH * KVH * NCHUNK * G];
__device__ float g_pl  [BATCH * KVH * NCHUNK * G];
__device__ float g_pacc[BATCH * KVH * NCHUNK * G * HEAD_DIM];
__device__ int   g_cnt [BATCH * KVH];   // fan-in counters (self-resetting)

// ---- packed fp32x2 helpers (Blackwell dual-rate fp32; PTX-only) ----
__device__ __forceinline__ ull fma2(ull a, ull b, ull c) {
    ull d;
    asm("fma.rn.f32x2 %0, %1, %2, %3;" : "=l"(d) : "l"(a), "l"(b), "l"(c));
    return d;
}
__device__ __forceinline__ ull mul2(ull a, ull b) {
    ull d;
    asm("mul.rn.f32x2 %0, %1, %2;" : "=l"(d) : "l"(a), "l"(b));
    return d;
}
__device__ __forceinline__ ull pack2(float lo, float hi) {
    ull d;
    asm("mov.b64 %0, {%1, %2};" : "=l"(d) : "f"(lo), "f"(hi));
    return d;
}
__device__ __forceinline__ float2 unpack2(ull a) {
    float lo, hi;
    asm("mov.b64 {%0, %1}, %2;" : "=f"(lo), "=f"(hi) : "l"(a));
    return make_float2(lo, hi);
}

__device__ __forceinline__ void cp16(uint32_t dst, const void* src) {
    asm volatile("cp.async.cg.shared.global [%0], [%1], 16;\n" :: "r"(dst), "l"(src));
}
__device__ __forceinline__ void cp_commit() {
    asm volatile("cp.async.commit_group;\n" ::);
}
template <int N>
__device__ __forceinline__ void cp_wait() {
    asm volatile("cp.async.wait_group %0;\n" :: "n"(N));
}

// Resolve base row pointer for token `flat` (cache or fresh k/v on override).
__device__ __forceinline__ const float* resolve_row(
    int flat, int ovr,
    const float* __restrict__ cache, const float* __restrict__ fresh,
    const int* sl_sh, int h)
{
    if (ovr) {
        int r = -1;
        #pragma unroll 4
        for (int j = 0; j < BATCH; j++)
            if (sl_sh[j] == flat) r = j;
        if (r >= 0) return fresh + ((size_t)r * KVH + h) * HEAD_DIM;
    }
    return cache + (size_t)flat * D_KV + (size_t)h * HEAD_DIM;
}

__device__ __forceinline__ void issue_k(
    int phys, int ovr, int row, int sl, uint32_t kdst,
    const float* __restrict__ kc, const float* __restrict__ knew,
    const int* sl_sh, int h)
{
    const int flat = phys * BLOCK_SZ + row;
    const float* krow = resolve_row(flat, ovr, kc, knew, sl_sh, h);
    const uint32_t kb = kdst + row * 512 + sl * 16;
    const char* kp = (const char*)krow + sl * 16;
    #pragma unroll
    for (int i = 0; i < 4; i++) cp16(kb + i * 128, kp + i * 128);
}

__device__ __forceinline__ void issue_v(
    int phys, int ovr, int row, int sl, uint32_t vdst,
    const float* __restrict__ vc, const float* __restrict__ vnew,
    const int* sl_sh, int h)
{
    const int flat = phys * BLOCK_SZ + row;
    const float* vrow = resolve_row(flat, ovr, vc, vnew, sl_sh, h);
    const uint32_t vb = vdst + row * 512 + sl * 16;
    const char* vp = (const char*)vrow + sl * 16;
    #pragma unroll
    for (int i = 0; i < 4; i++) cp16(vb + i * 128, vp + i * 128);
}

// ---------------------------------------------------------------------------
// Split-KV flash-decode with fused fan-in LSE reduce.
// grid = (NCHUNK, KVH, B), 128 threads.
// ---------------------------------------------------------------------------
__global__ void __launch_bounds__(128, 6) attn_kernel(
    const float* __restrict__ q,
    const float* __restrict__ knew,
    const float* __restrict__ vnew,
    const float* __restrict__ kc,
    const float* __restrict__ vc,
    const int*   __restrict__ bt,
    const int*   __restrict__ ctx_lens,
    const int*   __restrict__ slot,
    float* __restrict__ out)
{
    const int b     = blockIdx.z;
    const int h     = blockIdx.y;
    const int chunk = blockIdx.x;

    const int ctx   = ctx_lens[b];
    const int start = chunk * CHUNK;
    if (start >= ctx) return;
    const int end = (start + CHUNK < ctx) ? (start + CHUNK) : ctx;
    const int nb  = (end - start + BLOCK_SZ - 1) / BLOCK_SZ;
    const int nv  = (ctx + CHUNK - 1) / CHUNK;

    const int tid  = threadIdx.x;
    const int part = tid & 15;
    const int trow = tid >> 4;
    const int row  = tid >> 3;   // cp.async row
    const int sl   = tid & 7;    // cp.async 16B segment
    const int w    = tid >> 5;   // warp id (= head for softmax)
    const int lane = tid & 31;
    const int hsel = part & 3;

    __shared__ float k_sh[2][BLOCK_SZ][HEAD_DIM];
    __shared__ float v_sh[2][BLOCK_SZ][HEAD_DIM];
    __shared__ float s_sh[G][BLOCK_SZ];
    __shared__ __align__(16) float p_sh[BLOCK_SZ][G];
    __shared__ float st_m[G], st_l[G];
    __shared__ __align__(16) float alpha_sh[G];
    __shared__ int   ph_sh[NBLK];
    __shared__ int   ov_sh[NBLK];
    __shared__ int   sl_sh[BATCH];
    __shared__ int   is_last;

    // ---- prologue ----
    if (tid < BATCH) sl_sh[tid] = slot[tid];
    if (tid < nb)    ph_sh[tid] = bt[b * MAX_BPS + (start >> 4) + tid];
    if (tid < G)     { st_m[tid] = -3.0e38f; st_l[tid] = 0.0f; }
    __syncthreads();
    if (tid < nb) {
        const int p0 = ph_sh[tid] * BLOCK_SZ;
        int f = 0;
        for (int j = 0; j < BATCH; j++) {
            const int s = sl_sh[j];
            f |= (s >= p0) & (s < p0 + BLOCK_SZ);
        }
        ov_sh[tid] = f;
    }
    __syncthreads();

    const uint32_t kbase = (uint32_t)__cvta_generic_to_shared(&k_sh[0][0][0]);
    const uint32_t vbase = (uint32_t)__cvta_generic_to_shared(&v_sh[0][0][0]);

    // q packed as f32x2: 4 heads x 4 pairs (32 regs)
    ull q2[G][4];
    #pragma unroll
    for (int g = 0; g < G; g++) {
        const float4* qp = (const float4*)(q + ((size_t)b * NUM_HEADS + (size_t)(h * G + g)) * HEAD_DIM);
        const float4 q0 = qp[part];
        const float4 q1 = qp[16 + part];
        q2[g][0] = pack2(q0.x, q0.y);
        q2[g][1] = pack2(q0.z, q0.w);
        q2[g][2] = pack2(q1.x, q1.y);
        q2[g][3] = pack2(q1.z, q1.w);
    }

    ull acc01 = 0ULL, acc23 = 0ULL;   // packed accumulators {g0,g1},{g2,g3}

    // ---- prefetch depth 2, K and V as separate commit groups ----
    issue_k(ph_sh[0], ov_sh[0], row, sl, kbase, kc, knew, sl_sh, h); cp_commit();
    issue_v(ph_sh[0], ov_sh[0], row, sl, vbase, vc, vnew, sl_sh, h); cp_commit();
    if (nb > 1) {
        issue_k(ph_sh[1], ov_sh[1], row, sl, kbase + 8192, kc, knew, sl_sh, h); cp_commit();
        issue_v(ph_sh[1], ov_sh[1], row, sl, vbase + 8192, vc, vnew, sl_sh, h); cp_commit();
    }

    int buf = 0;
    for (int jj = 0; jj < nb; jj++) {
        const bool lastit = (jj == nb - 1);
        if (lastit) cp_wait<1>(); else cp_wait<3>();   // K(jj) resident
        __syncthreads();

        // ---- scores from k_sh[buf] (packed f32x2 dots) ----
        {
            const ulonglong2* ks2 = (const ulonglong2*)&k_sh[buf][0][0];
            float xs[2];
            #pragma unroll
            for (int tp = 0; tp < 2; tp++) {
                const int tok = trow + tp * 8;
                const ulonglong2 K0 = ks2[tok * 32 + part];
                const ulonglong2 K1 = ks2[tok * 32 + 16 + part];
                float s[G];
                #pragma unroll
                for (int g = 0; g < G; g++) {
                    ull d2 = fma2(q2[g][0], K0.x,
                             fma2(q2[g][1], K0.y,
                             fma2(q2[g][2], K1.x,
                             mul2(q2[g][3], K1.y))));
                    const float2 uv = unpack2(d2);
                    s[g] = uv.x + uv.y;
                }
                #pragma unroll
                for (int g = 0; g < G; g++) {
                    s[g] += __shfl_xor_sync(0xffffffffu, s[g], 1, 16);
                    s[g] += __shfl_xor_sync(0xffffffffu, s[g], 2, 16);
                }
                float x = (hsel == 0) ? s[0] : (hsel == 1) ? s[1] : (hsel == 2) ? s[2] : s[3];
                x += __shfl_xor_sync(0xffffffffu, x, 4, 16);
                x += __shfl_xor_sync(0xffffffffu, x, 8, 16);
                xs[tp] = x;
            }
            if (part < 4) {
                const int t0 = start + jj * BLOCK_SZ;
                s_sh[part][trow]     = (t0 + trow     < ctx) ? xs[0] * SCALE_F : -1.0e30f;
                s_sh[part][trow + 8] = (t0 + trow + 8 < ctx) ? xs[1] * SCALE_F : -1.0e30f;
            }
        }
        if (lastit) cp_wait<0>(); else cp_wait<2>();   // V(jj) resident
        __syncthreads();                               // s_sh + V visible

        // ---- 4-warp softmax: warp w = head w, lanes = tokens ----
        {
            const int tt = lane & 15;
            const float sv = s_sh[w][tt];
            float mb = sv;
            #pragma unroll
            for (int d = 8; d >= 1; d >>= 1)
                mb = fmaxf(mb, __shfl_xor_sync(0xffffffffu, mb, d, 16));
            const float m_old = st_m[w];
            const float m_new = fmaxf(m_old, mb);
            const float p = __expf(sv - m_new);
            if (lane < 16) p_sh[tt][w] = p;
            float sum = p;
            #pragma unroll
            for (int d = 8; d >= 1; d >>= 1)
                sum += __shfl_xor_sync(0xffffffffu, sum, d, 16);
            if (lane == 0) {
                const float alpha = __expf(m_old - m_new);
                st_l[w] = st_l[w] * alpha + sum;
                st_m[w] = m_new;
                alpha_sh[w] = alpha;
            }
        }
        __syncthreads();

        // ---- accumulate (packed f32x2): thread owns dim d = tid ----
        {
            const float4 a4 = *(const float4*)&alpha_sh[0];
            acc01 = mul2(acc01, pack2(a4.x, a4.y));
            acc23 = mul2(acc23, pack2(a4.z, a4.w));
            #pragma unroll
            for (int tt = 0; tt < BLOCK_SZ; tt++) {
                const ulonglong2 pp = *(const ulonglong2*)&p_sh[tt][0];
                const float vv = v_sh[buf][tt][tid];
                const ull vv2 = pack2(vv, vv);
                acc01 = fma2(pp.x, vv2, acc01);
                acc23 = fma2(pp.y, vv2, acc23);
            }
        }
        __syncthreads();

        if (jj + 2 < nb) {
            issue_k(ph_sh[jj + 2], ov_sh[jj + 2], row, sl,
                    kbase + buf * 8192, kc, knew, sl_sh, h); cp_commit();
            issue_v(ph_sh[jj + 2], ov_sh[jj + 2], row, sl,
                    vbase + buf * 8192, vc, vnew, sl_sh, h); cp_commit();
        }
        buf ^= 1;
    }

    const float2 a01 = unpack2(acc01);
    const float2 a23 = unpack2(acc23);
    float acc[G] = {a01.x, a01.y, a23.x, a23.y};

    if (nv == 1) {
        // single-chunk fast path
        #pragma unroll
        for (int g = 0; g < G; g++)
            out[((size_t)b * NUM_HEADS + (size_t)(h * G + g)) * HEAD_DIM + tid]
                = acc[g] / st_l[g];
        return;
    }

    // ---- write chunk partials ----
    const int base = ((b * KVH + h) * NCHUNK + chunk) * G;
    #pragma unroll
    for (int g = 0; g < G; g++)
        g_pacc[(size_t)(base + g) * HEAD_DIM + tid] = acc[g];
    if (tid < G) {
        g_pm[base + tid] = st_m[tid];
        g_pl[base + tid] = st_l[tid];
    }

    // ---- fan-in: last CTA of this (b,h) group performs the LSE combine ----
    __threadfence();
    __syncthreads();
    if (tid == 0) {
        const int old = atomicAdd(&g_cnt[b * KVH + h], 1);
        is_last = (old == nv - 1);
    }
    __syncthreads();
    if (!is_last) return;

    __threadfence();
    if (tid == 0) g_cnt[b * KVH + h] = 0;   // reset for next graph replay

    const int d = tid;
    #pragma unroll
    for (int g = 0; g < G; g++) {
        const int base0 = (b * KVH + h) * NCHUNK * G + g;
        float pm[NCHUNK], pl[NCHUNK];
        #pragma unroll
        for (int c = 0; c < NCHUNK; c++) {
            pm[c] = (c < nv) ? __ldcg(&g_pm[base0 + c * G]) : -3.0e38f;
            pl[c] = (c < nv) ? __ldcg(&g_pl[base0 + c * G]) : 0.0f;
        }
        float M = -3.0e38f;
        #pragma unroll
        for (int c = 0; c < NCHUNK; c++) M = fmaxf(M, pm[c]);
        float wgt[NCHUNK];
        float L = 0.0f;
        #pragma unroll
        for (int c = 0; c < NCHUNK; c++) {
            wgt[c] = (c < nv) ? __expf(pm[c] - M) : 0.0f;
            L += wgt[c] * pl[c];
        }
        float pa[NCHUNK];
        #pragma unroll
        for (int c = 0; c < NCHUNK; c++)
            pa[c] = (c < nv) ? __ldcg(&g_pacc[(size_t)(base0 + c * G) * HEAD_DIM + d]) : 0.0f;
        float o = 0.0f;
        #pragma unroll
        for (int c = 0; c < NCHUNK; c++) o += wgt[c] * pa[c];
        out[((size_t)b * NUM_HEADS + (size_t)(h * G + g)) * HEAD_DIM + d] = o / L;
    }
}

extern "C" void kernel_launch(void* const* d_in, const int* in_sizes, int n_in,
                              void* d_out, int out_size) {
    const float* q    = (const float*)d_in[0];
    const float* k    = (const float*)d_in[1];
    const float* v    = (const float*)d_in[2];
    const float* kc   = (const float*)d_in[3];
    const float* vc   = (const float*)d_in[4];
    const int*   slot = (const int*)d_in[5];
    const int*   bt   = (const int*)d_in[6];
    const int*   ctx  = (const int*)d_in[7];

    dim3 grid(NCHUNK, KVH, BATCH);
    attn_kernel<<<grid, 128>>>(q, k, v, kc, vc, bt, ctx, slot, (float*)d_out);
}

// round 15
// speedup vs baseline: 1.1479x; 1.1479x over previous
#include <cuda_runtime.h>
#include <math.h>
#include <stdint.h>

#define HEAD_DIM   128
#define NUM_HEADS  32
#define KVH        8
#define G          4
#define BLOCK_SZ   16
#define D_KV       (KVH * HEAD_DIM)
#define MAX_BPS    128
#define MAX_CTX    2048
#define BATCH      32
#define CHUNK      128
#define NCHUNK     (MAX_CTX / CHUNK)        // 16
#define NBLK       (CHUNK / BLOCK_SZ)       // 8
#define SCALE_F    0.08838834764831845f

__device__ float g_pm  [BATCH * KVH * NCHUNK * G];
__device__ float g_pl  [BATCH * KVH * NCHUNK * G];
__device__ float g_pacc[BATCH * KVH * NCHUNK * G * HEAD_DIM];

__device__ __forceinline__ float dot4(float4 a, float4 b) {
    return a.x * b.x + a.y * b.y + a.z * b.z + a.w * b.w;
}

__device__ __forceinline__ void cp16(uint32_t dst, const void* src) {
    asm volatile("cp.async.cg.shared.global [%0], [%1], 16;\n" :: "r"(dst), "l"(src));
}
__device__ __forceinline__ void cp_commit() {
    asm volatile("cp.async.commit_group;\n" ::);
}
template <int N>
__device__ __forceinline__ void cp_wait() {
    asm volatile("cp.async.wait_group %0;\n" :: "n"(N));
}

// Resolve base row pointer for token `flat` (cache or fresh k/v on override).
__device__ __forceinline__ const float* resolve_row(
    int flat, int ovr,
    const float* __restrict__ cache, const float* __restrict__ fresh,
    const int* sl_sh, int h)
{
    if (ovr) {
        int r = -1;
        #pragma unroll 4
        for (int j = 0; j < BATCH; j++)
            if (sl_sh[j] == flat) r = j;
        if (r >= 0) return fresh + ((size_t)r * KVH + h) * HEAD_DIM;
    }
    return cache + (size_t)flat * D_KV + (size_t)h * HEAD_DIM;
}

__device__ __forceinline__ void issue_k(
    int phys, int ovr, int row, int sl, uint32_t kdst,
    const float* __restrict__ kc, const float* __restrict__ knew,
    const int* sl_sh, int h)
{
    const int flat = phys * BLOCK_SZ + row;
    const float* krow = resolve_row(flat, ovr, kc, knew, sl_sh, h);
    const uint32_t kb = kdst + row * 512 + sl * 16;
    const char* kp = (const char*)krow + sl * 16;
    #pragma unroll
    for (int i = 0; i < 4; i++) cp16(kb + i * 128, kp + i * 128);
}

__device__ __forceinline__ void issue_v(
    int phys, int ovr, int row, int sl, uint32_t vdst,
    const float* __restrict__ vc, const float* __restrict__ vnew,
    const int* sl_sh, int h)
{
    const int flat = phys * BLOCK_SZ + row;
    const float* vrow = resolve_row(flat, ovr, vc, vnew, sl_sh, h);
    const uint32_t vb = vdst + row * 512 + sl * 16;
    const char* vp = (const char*)vrow + sl * 16;
    #pragma unroll
    for (int i = 0; i < 4; i++) cp16(vb + i * 128, vp + i * 128);
}

// ---------------------------------------------------------------------------
// Split-KV flash-decode. grid = (NCHUNK, KVH, B), 128 threads.
// Scores: part = tid&15 owns 8 dims; trow = tid>>4 handles tokens trow,trow+8.
// Accumulate: thread = output dim.
// ---------------------------------------------------------------------------
__global__ void __launch_bounds__(128, 6) attn_kernel(
    const float* __restrict__ q,
    const float* __restrict__ knew,
    const float* __restrict__ vnew,
    const float* __restrict__ kc,
    const float* __restrict__ vc,
    const int*   __restrict__ bt,
    const int*   __restrict__ ctx_lens,
    const int*   __restrict__ slot,
    float* __restrict__ out)
{
    const int b     = blockIdx.z;
    const int h     = blockIdx.y;
    const int chunk = blockIdx.x;

    const int ctx   = ctx_lens[b];
    const int start = chunk * CHUNK;
    if (start >= ctx) return;
    const int end = (start + CHUNK < ctx) ? (start + CHUNK) : ctx;
    const int nb  = (end - start + BLOCK_SZ - 1) / BLOCK_SZ;
    const int nv  = (ctx + CHUNK - 1) / CHUNK;

    const int tid  = threadIdx.x;
    const int part = tid & 15;
    const int trow = tid >> 4;
    const int row  = tid >> 3;   // cp.async row
    const int sl   = tid & 7;    // cp.async 16B segment
    const int hsel = part & 3;

    __shared__ float k_sh[2][BLOCK_SZ][HEAD_DIM];
    __shared__ float v_sh[2][BLOCK_SZ][HEAD_DIM];
    __shared__ float s_sh[G][BLOCK_SZ];
    __shared__ __align__(16) float p_sh[BLOCK_SZ][G];
    __shared__ float st_m[G], st_l[G];
    __shared__ __align__(16) float alpha_sh[G];
    __shared__ int   ph_sh[NBLK];
    __shared__ int   ov_sh[NBLK];
    __shared__ int   sl_sh[BATCH];

    // ---- prologue ----
    if (tid < BATCH) sl_sh[tid] = slot[tid];
    if (tid < nb)    ph_sh[tid] = bt[b * MAX_BPS + (start >> 4) + tid];
    if (tid < G)     { st_m[tid] = -3.0e38f; st_l[tid] = 0.0f; }
    __syncthreads();
    if (tid < nb) {
        const int p0 = ph_sh[tid] * BLOCK_SZ;
        int f = 0;
        for (int j = 0; j < BATCH; j++) {
            const int s = sl_sh[j];
            f |= (s >= p0) & (s < p0 + BLOCK_SZ);
        }
        ov_sh[tid] = f;
    }
    __syncthreads();

    const uint32_t kbase = (uint32_t)__cvta_generic_to_shared(&k_sh[0][0][0]);
    const uint32_t vbase = (uint32_t)__cvta_generic_to_shared(&v_sh[0][0][0]);

    // q: 4 heads x 8 dims per thread (32 regs)
    float4 qr[G][2];
    #pragma unroll
    for (int g = 0; g < G; g++) {
        const float4* qp = (const float4*)(q + ((size_t)b * NUM_HEADS + (size_t)(h * G + g)) * HEAD_DIM);
        qr[g][0] = qp[part];
        qr[g][1] = qp[16 + part];
    }

    float acc[G] = {0.f, 0.f, 0.f, 0.f};

    // ---- prefetch depth 2; K and V in separate commit groups ----
    issue_k(ph_sh[0], ov_sh[0], row, sl, kbase, kc, knew, sl_sh, h); cp_commit();
    issue_v(ph_sh[0], ov_sh[0], row, sl, vbase, vc, vnew, sl_sh, h); cp_commit();
    if (nb > 1) {
        issue_k(ph_sh[1], ov_sh[1], row, sl, kbase + 8192, kc, knew, sl_sh, h); cp_commit();
        issue_v(ph_sh[1], ov_sh[1], row, sl, vbase + 8192, vc, vnew, sl_sh, h); cp_commit();
    }

    int buf = 0;
    for (int jj = 0; jj < nb; jj++) {
        const bool lastit = (jj == nb - 1);
        if (lastit) cp_wait<1>(); else cp_wait<3>();   // K(jj) resident
        __syncthreads();

        // ---- scores from k_sh[buf] ----
        {
            const float4* ks4 = (const float4*)&k_sh[buf][0][0];
            float xs[2];
            #pragma unroll
            for (int tp = 0; tp < 2; tp++) {
                const int tok = trow + tp * 8;
                const float4 k0 = ks4[tok * 32 + part];
                const float4 k1 = ks4[tok * 32 + 16 + part];
                float s0 = dot4(qr[0][0], k0) + dot4(qr[0][1], k1);
                float s1 = dot4(qr[1][0], k0) + dot4(qr[1][1], k1);
                float s2 = dot4(qr[2][0], k0) + dot4(qr[2][1], k1);
                float s3 = dot4(qr[3][0], k0) + dot4(qr[3][1], k1);
                s0 += __shfl_xor_sync(0xffffffffu, s0, 1, 16);
                s1 += __shfl_xor_sync(0xffffffffu, s1, 1, 16);
                s2 += __shfl_xor_sync(0xffffffffu, s2, 1, 16);
                s3 += __shfl_xor_sync(0xffffffffu, s3, 1, 16);
                s0 += __shfl_xor_sync(0xffffffffu, s0, 2, 16);
                s1 += __shfl_xor_sync(0xffffffffu, s1, 2, 16);
                s2 += __shfl_xor_sync(0xffffffffu, s2, 2, 16);
                s3 += __shfl_xor_sync(0xffffffffu, s3, 2, 16);
                float x = (hsel == 0) ? s0 : (hsel == 1) ? s1 : (hsel == 2) ? s2 : s3;
                x += __shfl_xor_sync(0xffffffffu, x, 4, 16);
                x += __shfl_xor_sync(0xffffffffu, x, 8, 16);
                xs[tp] = x;
            }
            if (part < 4) {
                const int t0 = start + jj * BLOCK_SZ;
                s_sh[part][trow]     = (t0 + trow     < ctx) ? xs[0] * SCALE_F : -1.0e30f;
                s_sh[part][trow + 8] = (t0 + trow + 8 < ctx) ? xs[1] * SCALE_F : -1.0e30f;
            }
        }
        if (lastit) cp_wait<0>(); else cp_wait<2>();   // V(jj) resident
        __syncthreads();                               // s_sh + V visible

        // ---- parallel softmax: 64 threads = 4 heads x 16 tokens ----
        if (tid < 64) {
            const int g  = tid >> 4;
            const int tt = tid & 15;
            const float sv = s_sh[g][tt];
            float mb = sv;
            #pragma unroll
            for (int d = 8; d >= 1; d >>= 1)
                mb = fmaxf(mb, __shfl_xor_sync(0xffffffffu, mb, d, 16));
            const float m_old = st_m[g];
            const float m_new = fmaxf(m_old, mb);
            const float p = __expf(sv - m_new);
            p_sh[tt][g] = p;
            float sum = p;
            #pragma unroll
            for (int d = 8; d >= 1; d >>= 1)
                sum += __shfl_xor_sync(0xffffffffu, sum, d, 16);
            if (tt == 0) {
                const float alpha = __expf(m_old - m_new);
                st_l[g] = st_l[g] * alpha + sum;
                st_m[g] = m_new;
                alpha_sh[g] = alpha;
            }
        }
        __syncthreads();

        // ---- accumulate: thread owns dim d = tid; p via float4 broadcast ----
        {
            const float4 a4 = *(const float4*)&alpha_sh[0];
            acc[0] *= a4.x; acc[1] *= a4.y; acc[2] *= a4.z; acc[3] *= a4.w;
            #pragma unroll
            for (int tt = 0; tt < BLOCK_SZ; tt++) {
                const float4 p4 = *(const float4*)&p_sh[tt][0];
                const float vv = v_sh[buf][tt][tid];
                acc[0] += p4.x * vv;
                acc[1] += p4.y * vv;
                acc[2] += p4.z * vv;
                acc[3] += p4.w * vv;
            }
        }
        __syncthreads();

        if (jj + 2 < nb) {
            issue_k(ph_sh[jj + 2], ov_sh[jj + 2], row, sl,
                    kbase + buf * 8192, kc, knew, sl_sh, h); cp_commit();
            issue_v(ph_sh[jj + 2], ov_sh[jj + 2], row, sl,
                    vbase + buf * 8192, vc, vnew, sl_sh, h); cp_commit();
        }
        buf ^= 1;
    }

    if (nv == 1) {
        // single-chunk fast path: write final output directly
        #pragma unroll
        for (int g = 0; g < G; g++)
            out[((size_t)b * NUM_HEADS + (size_t)(h * G + g)) * HEAD_DIM + tid]
                = acc[g] / st_l[g];
        return;
    }

    // ---- write chunk partials ----
    const int base = ((b * KVH + h) * NCHUNK + chunk) * G;
    #pragma unroll
    for (int g = 0; g < G; g++)
        g_pacc[(size_t)(base + g) * HEAD_DIM + tid] = acc[g];
    if (tid < G) {
        g_pm[base + tid] = st_m[tid];
        g_pl[base + tid] = st_l[tid];
    }
}

// ---------------------------------------------------------------------------
// Combine chunk partials (log-sum-exp), batched independent loads.
// grid = B*KVH*G, block = 128 (thread = dim).
// ---------------------------------------------------------------------------
__global__ void __launch_bounds__(128) reduce_kernel(
    float* __restrict__ out, const int* __restrict__ ctx_lens)
{
    const int idx = blockIdx.x;
    const int g   = idx & (G - 1);
    const int bh  = idx >> 2;
    const int b   = bh / KVH;
    const int h   = bh % KVH;
    const int d   = threadIdx.x;

    const int ctx = ctx_lens[b];
    const int nv  = (ctx + CHUNK - 1) / CHUNK;
    if (nv == 1) return;   // attn kernel wrote output directly

    const int base0 = (b * KVH + h) * NCHUNK * G + g;

    float pm[NCHUNK], pl[NCHUNK];
    #pragma unroll
    for (int c = 0; c < NCHUNK; c++) {
        pm[c] = (c < nv) ? __ldg(&g_pm[base0 + c * G]) : -3.0e38f;
        pl[c] = (c < nv) ? __ldg(&g_pl[base0 + c * G]) : 0.0f;
    }

    float M = -3.0e38f;
    #pragma unroll
    for (int c = 0; c < NCHUNK; c++) M = fmaxf(M, pm[c]);

    float wgt[NCHUNK];
    float L = 0.0f;
    #pragma unroll
    for (int c = 0; c < NCHUNK; c++) {
        wgt[c] = (c < nv) ? __expf(pm[c] - M) : 0.0f;
        L += wgt[c] * pl[c];
    }

    float pa[NCHUNK];
    #pragma unroll
    for (int c = 0; c < NCHUNK; c++)
        pa[c] = (c < nv) ? __ldg(&g_pacc[(size_t)(base0 + c * G) * HEAD_DIM + d]) : 0.0f;

    float o = 0.0f;
    #pragma unroll
    for (int c = 0; c < NCHUNK; c++) o += wgt[c] * pa[c];

    out[((size_t)b * NUM_HEADS + (size_t)(h * G + g)) * HEAD_DIM + d] = o / L;
}

extern "C" void kernel_launch(void* const* d_in, const int* in_sizes, int n_in,
                              void* d_out, int out_size) {
    const float* q    = (const float*)d_in[0];
    const float* k    = (const float*)d_in[1];
    const float* v    = (const float*)d_in[2];
    const float* kc   = (const float*)d_in[3];
    const float* vc   = (const float*)d_in[4];
    const int*   slot = (const int*)d_in[5];
    const int*   bt   = (const int*)d_in[6];
    const int*   ctx  = (const int*)d_in[7];

    dim3 grid(NCHUNK, KVH, BATCH);
    attn_kernel<<<grid, 128>>>(q, k, v, kc, vc, bt, ctx, slot, (float*)d_out);

    reduce_kernel<<<BATCH * KVH * G, HEAD_DIM>>>((float*)d_out, ctx);
}